// round 4
// baseline (speedup 1.0000x reference)
#include <cuda_runtime.h>
#include <cstdint>

// Problem constants
#define B_    4
#define L_    1024
#define V_    1280
#define E_    768
#define NBIN  8
#define NHID  32

// Output layout: concat(logits[B,L,8,V], tte[B,L,V], mask[B,L,8,V]) fp32
#define TTE_OFF    ((size_t)B_ * L_ * NBIN * V_)                 // 41943040
#define MASK_OFF   (TTE_OFF + (size_t)B_ * L_ * V_)              // 47185920

// Scratch: x = h @ W1, stored TRANSPOSED per row: g_x[row*256 + h*8 + n]
__device__ float g_x[(size_t)B_ * L_ * NBIN * NHID];
// Seed table: next-occurrence index of v at or after each 32-row boundary
// g_seed[b][chunk][v], chunk in [0,32)
__device__ int g_seed[(size_t)B_ * 32 * V_];

typedef unsigned long long u64;
union F4U2 { float4 f; u64 u[2]; };

__device__ __forceinline__ u64 pk(float lo, float hi) {
    u64 r; asm("mov.b64 %0, {%1,%2};" : "=l"(r) : "f"(lo), "f"(hi)); return r;
}
__device__ __forceinline__ void upk(u64 v, float& lo, float& hi) {
    asm("mov.b64 {%0,%1}, %2;" : "=f"(lo), "=f"(hi) : "l"(v));
}
__device__ __forceinline__ void fma2(u64& d, u64 a, u64 b) {
    asm("fma.rn.f32x2 %0, %1, %2, %0;" : "+l"(d) : "l"(a), "l"(b));
}

// ---------------------------------------------------------------------------
// Kernel 1: x = h @ W1   (M=4096, K=768, N=256).  128x64 tile, 256 threads,
// 8x4 per thread, diagonal-packed FFMA2.  Writes g_x in [h][bin] layout.
// ---------------------------------------------------------------------------
__global__ __launch_bounds__(256) void k_gemm1(const float* __restrict__ A,
                                               const float* __restrict__ W1) {
    __shared__ float As[16][132];   // [k][row]
    __shared__ float Bs[16][68];    // [k][col]
    const int K = E_, N = NBIN * NHID;
    int bx = blockIdx.x;                 // 0..3   (N/64)
    int by = blockIdx.y;                 // 0..31  (M/128)
    int tid = threadIdx.x;
    int tx = tid & 15, ty = tid >> 4;
    int rowBase = by * 128, colBase = bx * 64;

    u64 c[4][4];
#pragma unroll
    for (int i = 0; i < 4; i++)
#pragma unroll
        for (int j = 0; j < 4; j++) c[i][j] = 0;

    for (int k0 = 0; k0 < K; k0 += 16) {
#pragma unroll
        for (int p = 0; p < 8; p++) {          // 128x16 A tile
            int idx = tid + p * 256;
            int r = idx >> 4, cc = idx & 15;
            As[cc][r] = A[(size_t)(rowBase + r) * K + k0 + cc];
        }
#pragma unroll
        for (int p = 0; p < 4; p++) {          // 16x64 B tile
            int idx = tid + p * 256;
            int r = idx >> 6, cc = idx & 63;
            Bs[r][cc] = W1[(size_t)(k0 + r) * N + colBase + cc];
        }
        __syncthreads();
#pragma unroll
        for (int kk = 0; kk < 16; kk++) {
            F4U2 alo, ahi, bv;
            alo.f = *(const float4*)&As[kk][ty * 8];
            ahi.f = *(const float4*)&As[kk][ty * 8 + 4];
            bv.f  = *(const float4*)&Bs[kk][tx * 4];
            u64 ap0 = alo.u[0], ap1 = alo.u[1], ap2 = ahi.u[0], ap3 = ahi.u[1];
            u64 b01 = bv.u[0], b23 = bv.u[1];
            u64 b12 = pk(bv.f.y, bv.f.z);
            u64 b30 = pk(bv.f.w, bv.f.x);
            fma2(c[0][0], ap0, b01); fma2(c[0][1], ap0, b12);
            fma2(c[0][2], ap0, b23); fma2(c[0][3], ap0, b30);
            fma2(c[1][0], ap1, b01); fma2(c[1][1], ap1, b12);
            fma2(c[1][2], ap1, b23); fma2(c[1][3], ap1, b30);
            fma2(c[2][0], ap2, b01); fma2(c[2][1], ap2, b12);
            fma2(c[2][2], ap2, b23); fma2(c[2][3], ap2, b30);
            fma2(c[3][0], ap3, b01); fma2(c[3][1], ap3, b12);
            fma2(c[3][2], ap3, b23); fma2(c[3][3], ap3, b30);
        }
        __syncthreads();
    }

    // Unpack diagonal pairs: c[rp][0]=(o[2rp][0],o[2rp+1][1]), [1]=(.,1/.,2),
    // [2]=(.,2/.,3), [3]=(.,3/.,0)
    float o[8][4];
#pragma unroll
    for (int rp = 0; rp < 4; rp++) {
        upk(c[rp][0], o[2*rp][0], o[2*rp+1][1]);
        upk(c[rp][1], o[2*rp][1], o[2*rp+1][2]);
        upk(c[rp][2], o[2*rp][2], o[2*rp+1][3]);
        upk(c[rp][3], o[2*rp][3], o[2*rp+1][0]);
    }
#pragma unroll
    for (int rr = 0; rr < 8; rr++) {
        size_t rbase = (size_t)(rowBase + ty * 8 + rr) * 256;
#pragma unroll
        for (int j = 0; j < 4; j++) {
            int col = colBase + tx * 4 + j;       // original col = n*32+h
            int pc = (col & 31) * 8 + (col >> 5); // transposed [h][n]
            g_x[rbase + pc] = o[rr][j];
        }
    }
}

// ---------------------------------------------------------------------------
// Kernel 2a: seed scan.  grid (vb=5, b=4), 256 threads, 1 v per thread.
// Backward scan over L; at each 32-boundary record the next-occurrence state.
// ---------------------------------------------------------------------------
__global__ __launch_bounds__(256) void k_seed(const int* __restrict__ targets) {
    __shared__ int tg[L_];
    int b = blockIdx.y;
    int v = blockIdx.x * 256 + threadIdx.x;
    for (int i = threadIdx.x; i < L_; i += 256)
        tg[i] = targets[(size_t)b * L_ + i];
    __syncthreads();

    int* seed = g_seed + (size_t)b * 32 * V_;
    int nxt = L_;
#pragma unroll 1
    for (int ch = 31; ch >= 0; --ch) {
        seed[(size_t)ch * V_ + v] = nxt;   // occurrences at index >= (ch+1)*32
#pragma unroll
        for (int ii = 31; ii >= 0; --ii) {
            int i = ch * 32 + ii;
            if (tg[i] == v) nxt = i;
        }
    }
}

// ---------------------------------------------------------------------------
// Kernel 2b: tte + mask writer.  grid (vb=2, chunk=32, b=4), 160 threads,
// 4 consecutive v per thread, 32 rows per block, all stores STG.128.
// Special case (scatter semantics): token_index[b, i>=1, v=0] = 0.
// ---------------------------------------------------------------------------
__global__ __launch_bounds__(160) void k_tte_write(const int* __restrict__ targets,
                                                   const float* __restrict__ age,
                                                   const float* __restrict__ targets_age,
                                                   float* __restrict__ out) {
    __shared__ float ta[L_];
    __shared__ float ag_s[32];
    __shared__ int   tg_s[32];

    int b     = blockIdx.z;
    int chunk = blockIdx.y;          // 0..31
    int i0    = chunk * 32;
    int v0    = 4 * (blockIdx.x * 160 + threadIdx.x);

    for (int i = threadIdx.x; i < L_; i += 160)
        ta[i] = targets_age[(size_t)b * L_ + i];
    if (threadIdx.x < 32) {
        ag_s[threadIdx.x] = age[(size_t)b * L_ + i0 + threadIdx.x];
        tg_s[threadIdx.x] = targets[(size_t)b * L_ + i0 + threadIdx.x];
    }
    __syncthreads();

    int4 sd = *(const int4*)&g_seed[((size_t)b * 32 + chunk) * V_ + v0];
    int nxt[4] = {sd.x, sd.y, sd.z, sd.w};

    float* out_tte  = out + TTE_OFF  + (size_t)b * L_ * V_;
    float* out_mask = out + MASK_OFF + (size_t)b * L_ * NBIN * V_;
    bool isv0 = (v0 == 0);

    for (int ii = 31; ii >= 0; --ii) {
        int i = i0 + ii;
        int t = tg_s[ii];
#pragma unroll
        for (int k = 0; k < 4; k++)
            if (t == v0 + k) nxt[k] = i;

        float a = ag_s[ii];
        float tt[4]; bool ne[4];
#pragma unroll
        for (int k = 0; k < 4; k++) {
            int idx = nxt[k];
            if (isv0 && k == 0 && i >= 1) idx = 0;
            ne[k] = (idx == L_);
            tt[k] = ta[ne[k] ? (L_ - 1) : idx] - a;
        }
        *(float4*)&out_tte[(size_t)i * V_ + v0] = make_float4(tt[0], tt[1], tt[2], tt[3]);

        size_t mbase = (size_t)i * NBIN * V_ + v0;
#pragma unroll
        for (int n = 0; n < NBIN; n++) {
            float lo = 1.25f * n;
            float hi = 1.25f * (n + 1);
            float4 m;
            m.x = ((tt[0] >= lo && tt[0] < hi) || ne[0]) ? 1.0f : 0.0f;
            m.y = ((tt[1] >= lo && tt[1] < hi) || ne[1]) ? 1.0f : 0.0f;
            m.z = ((tt[2] >= lo && tt[2] < hi) || ne[2]) ? 1.0f : 0.0f;
            m.w = ((tt[3] >= lo && tt[3] < hi) || ne[3]) ? 1.0f : 0.0f;
            *(float4*)&out_mask[mbase + (size_t)n * V_] = m;
        }
    }
}

// ---------------------------------------------------------------------------
// Kernel 3: logits = x @ W2 per bin.  Block = 8 rows, thread = one v.
// Bin pairs contiguous u64 in xs ([h][bin] layout) x replicated w2 -> FFMA2.
// ---------------------------------------------------------------------------
#define R3 8
__global__ __launch_bounds__(256) void k_gemm2(const float* __restrict__ W2,
                                               float* __restrict__ out) {
    __shared__ float xs[R3][256];
    int rowBase = blockIdx.x * R3;

    const float4* xsrc = (const float4*)(g_x + (size_t)rowBase * 256);
    float4* xsF = (float4*)xs;
#pragma unroll
    for (int i = 0; i < 2; i++) xsF[threadIdx.x + i * 256] = xsrc[threadIdx.x + i * 256];
    __syncthreads();

    for (int it = 0; it < 5; ++it) {
        int v = it * 256 + threadIdx.x;
        u64 w2r[32];
#pragma unroll
        for (int h = 0; h < 32; h++) {
            float w = W2[(size_t)h * V_ + v];
            w2r[h] = pk(w, w);
        }

        for (int r = 0; r < R3; r++) {
            u64 acc0 = 0, acc1 = 0, acc2 = 0, acc3 = 0;
#pragma unroll
            for (int h = 0; h < 32; h++) {
                F4U2 qa, qb;
                qa.f = *(const float4*)&xs[r][h * 8];
                qb.f = *(const float4*)&xs[r][h * 8 + 4];
                fma2(acc0, qa.u[0], w2r[h]);
                fma2(acc1, qa.u[1], w2r[h]);
                fma2(acc2, qb.u[0], w2r[h]);
                fma2(acc3, qb.u[1], w2r[h]);
            }
            float o[8];
            upk(acc0, o[0], o[1]);
            upk(acc1, o[2], o[3]);
            upk(acc2, o[4], o[5]);
            upk(acc3, o[6], o[7]);
            size_t obase = (size_t)(rowBase + r) * NBIN * V_ + v;
#pragma unroll
            for (int n = 0; n < NBIN; n++)
                out[obase + (size_t)n * V_] = o[n];
        }
    }
}

// ---------------------------------------------------------------------------
static cudaStream_t g_s2;
static cudaEvent_t g_e1, g_e2;
static struct StreamInit {
    StreamInit() {
        cudaStreamCreateWithFlags(&g_s2, cudaStreamNonBlocking);
        cudaEventCreateWithFlags(&g_e1, cudaEventDisableTiming);
        cudaEventCreateWithFlags(&g_e2, cudaEventDisableTiming);
    }
} g_stream_init;

extern "C" void kernel_launch(void* const* d_in, const int* in_sizes, int n_in,
                              void* d_out, int out_size) {
    const float* h       = (const float*)d_in[0];  // (B,L,768)
    const float* age     = (const float*)d_in[1];  // (B,L)
    const float* tage    = (const float*)d_in[2];  // (B,L)
    // d_in[3] = delta_t (unused by the outputs)
    const int*   targets = (const int*)d_in[4];    // (B,L) int32
    const float* W1      = (const float*)d_in[5];  // (768,256)
    const float* W2      = (const float*)d_in[6];  // (32,1280)
    float* out = (float*)d_out;

    // Fork: tte/mask path (store-BW bound) vs GEMM path (fma bound).
    cudaEventRecord(g_e1, 0);
    cudaStreamWaitEvent(g_s2, g_e1, 0);
    k_seed<<<dim3(5, B_), 256, 0, g_s2>>>(targets);
    k_tte_write<<<dim3(2, 32, B_), 160, 0, g_s2>>>(targets, age, tage, out);

    k_gemm1<<<dim3(4, 32), 256>>>(h, W1);
    k_gemm2<<<(B_ * L_) / R3, 256>>>(W2, out);

    cudaEventRecord(g_e2, g_s2);
    cudaStreamWaitEvent(0, g_e2, 0);
}

// round 5
// speedup vs baseline: 1.0963x; 1.0963x over previous
#include <cuda_runtime.h>
#include <cstdint>

// Problem constants
#define B_    4
#define L_    1024
#define V_    1280
#define E_    768
#define NBIN  8
#define NHID  32

// Output layout: concat(logits[B,L,8,V], tte[B,L,V], mask[B,L,8,V]) fp32
#define TTE_OFF    ((size_t)B_ * L_ * NBIN * V_)                 // 41943040
#define MASK_OFF   (TTE_OFF + (size_t)B_ * L_ * V_)              // 47185920

// Scratch: x = h @ W1, stored TRANSPOSED per row: g_x[row*256 + h*8 + n]
__device__ float g_x[(size_t)B_ * L_ * NBIN * NHID];
// Seed table: next-occurrence index of v at or after each 32-row boundary
__device__ int g_seed[(size_t)B_ * 32 * V_];

typedef unsigned long long u64;
union F4U2 { float4 f; u64 u[2]; };

__device__ __forceinline__ u64 pk(float lo, float hi) {
    u64 r; asm("mov.b64 %0, {%1,%2};" : "=l"(r) : "f"(lo), "f"(hi)); return r;
}
__device__ __forceinline__ void upk(u64 v, float& lo, float& hi) {
    asm("mov.b64 {%0,%1}, %2;" : "=f"(lo), "=f"(hi) : "l"(v));
}
__device__ __forceinline__ void fma2(u64& d, u64 a, u64 b) {
    asm("fma.rn.f32x2 %0, %1, %2, %0;" : "+l"(d) : "l"(a), "l"(b));
}

// ---------------------------------------------------------------------------
// Kernel 1: x = h @ W1   (M=4096, K=768, N=256).  128x64 tile, 256 threads,
// 8x4 per thread, diagonal-packed FFMA2.  Writes g_x in [h][bin] layout.
// ---------------------------------------------------------------------------
__global__ __launch_bounds__(256) void k_gemm1(const float* __restrict__ A,
                                               const float* __restrict__ W1) {
    __shared__ float As[16][132];   // [k][row]
    __shared__ float Bs[16][68];    // [k][col]
    const int K = E_, N = NBIN * NHID;
    int bx = blockIdx.x;                 // 0..3   (N/64)
    int by = blockIdx.y;                 // 0..31  (M/128)
    int tid = threadIdx.x;
    int tx = tid & 15, ty = tid >> 4;
    int rowBase = by * 128, colBase = bx * 64;

    u64 c[4][4];
#pragma unroll
    for (int i = 0; i < 4; i++)
#pragma unroll
        for (int j = 0; j < 4; j++) c[i][j] = 0;

    for (int k0 = 0; k0 < K; k0 += 16) {
#pragma unroll
        for (int p = 0; p < 8; p++) {          // 128x16 A tile
            int idx = tid + p * 256;
            int r = idx >> 4, cc = idx & 15;
            As[cc][r] = A[(size_t)(rowBase + r) * K + k0 + cc];
        }
#pragma unroll
        for (int p = 0; p < 4; p++) {          // 16x64 B tile
            int idx = tid + p * 256;
            int r = idx >> 6, cc = idx & 63;
            Bs[r][cc] = W1[(size_t)(k0 + r) * N + colBase + cc];
        }
        __syncthreads();
#pragma unroll
        for (int kk = 0; kk < 16; kk++) {
            F4U2 alo, ahi, bv;
            alo.f = *(const float4*)&As[kk][ty * 8];
            ahi.f = *(const float4*)&As[kk][ty * 8 + 4];
            bv.f  = *(const float4*)&Bs[kk][tx * 4];
            u64 ap0 = alo.u[0], ap1 = alo.u[1], ap2 = ahi.u[0], ap3 = ahi.u[1];
            u64 b01 = bv.u[0], b23 = bv.u[1];
            u64 b12 = pk(bv.f.y, bv.f.z);
            u64 b30 = pk(bv.f.w, bv.f.x);
            fma2(c[0][0], ap0, b01); fma2(c[0][1], ap0, b12);
            fma2(c[0][2], ap0, b23); fma2(c[0][3], ap0, b30);
            fma2(c[1][0], ap1, b01); fma2(c[1][1], ap1, b12);
            fma2(c[1][2], ap1, b23); fma2(c[1][3], ap1, b30);
            fma2(c[2][0], ap2, b01); fma2(c[2][1], ap2, b12);
            fma2(c[2][2], ap2, b23); fma2(c[2][3], ap2, b30);
            fma2(c[3][0], ap3, b01); fma2(c[3][1], ap3, b12);
            fma2(c[3][2], ap3, b23); fma2(c[3][3], ap3, b30);
        }
        __syncthreads();
    }

    float o[8][4];
#pragma unroll
    for (int rp = 0; rp < 4; rp++) {
        upk(c[rp][0], o[2*rp][0], o[2*rp+1][1]);
        upk(c[rp][1], o[2*rp][1], o[2*rp+1][2]);
        upk(c[rp][2], o[2*rp][2], o[2*rp+1][3]);
        upk(c[rp][3], o[2*rp][3], o[2*rp+1][0]);
    }
#pragma unroll
    for (int rr = 0; rr < 8; rr++) {
        size_t rbase = (size_t)(rowBase + ty * 8 + rr) * 256;
#pragma unroll
        for (int j = 0; j < 4; j++) {
            int col = colBase + tx * 4 + j;       // original col = n*32+h
            int pc = (col & 31) * 8 + (col >> 5); // transposed [h][n]
            g_x[rbase + pc] = o[rr][j];
        }
    }
}

// ---------------------------------------------------------------------------
// Kernel 2a: seed scan.  grid (vb=5, b=4), 256 threads, 1 v per thread.
// ---------------------------------------------------------------------------
__global__ __launch_bounds__(256) void k_seed(const int* __restrict__ targets) {
    __shared__ int tg[L_];
    int b = blockIdx.y;
    int v = blockIdx.x * 256 + threadIdx.x;
    for (int i = threadIdx.x; i < L_; i += 256)
        tg[i] = targets[(size_t)b * L_ + i];
    __syncthreads();

    int* seed = g_seed + (size_t)b * 32 * V_;
    int nxt = L_;
#pragma unroll 1
    for (int ch = 31; ch >= 0; --ch) {
        seed[(size_t)ch * V_ + v] = nxt;
#pragma unroll
        for (int ii = 31; ii >= 0; --ii) {
            int i = ch * 32 + ii;
            if (tg[i] == v) nxt = i;
        }
    }
}

// ---------------------------------------------------------------------------
// Kernel 2b: tte + mask writer.  grid (vb=2, chunk=32, b=4), 160 threads,
// 4 consecutive v per thread, 32 rows per block, all stores STG.128.
// Special case (scatter semantics): token_index[b, i>=1, v=0] = 0.
// ---------------------------------------------------------------------------
__global__ __launch_bounds__(160) void k_tte_write(const int* __restrict__ targets,
                                                   const float* __restrict__ age,
                                                   const float* __restrict__ targets_age,
                                                   float* __restrict__ out) {
    __shared__ float ta[L_];
    __shared__ float ag_s[32];
    __shared__ int   tg_s[32];

    int b     = blockIdx.z;
    int chunk = blockIdx.y;          // 0..31
    int i0    = chunk * 32;
    int v0    = 4 * (blockIdx.x * 160 + threadIdx.x);

    for (int i = threadIdx.x; i < L_; i += 160)
        ta[i] = targets_age[(size_t)b * L_ + i];
    if (threadIdx.x < 32) {
        ag_s[threadIdx.x] = age[(size_t)b * L_ + i0 + threadIdx.x];
        tg_s[threadIdx.x] = targets[(size_t)b * L_ + i0 + threadIdx.x];
    }
    __syncthreads();

    int4 sd = *(const int4*)&g_seed[((size_t)b * 32 + chunk) * V_ + v0];
    int nxt[4] = {sd.x, sd.y, sd.z, sd.w};

    float* out_tte  = out + TTE_OFF  + (size_t)b * L_ * V_;
    float* out_mask = out + MASK_OFF + (size_t)b * L_ * NBIN * V_;
    bool isv0 = (v0 == 0);

    for (int ii = 31; ii >= 0; --ii) {
        int i = i0 + ii;
        int t = tg_s[ii];
#pragma unroll
        for (int k = 0; k < 4; k++)
            if (t == v0 + k) nxt[k] = i;

        float a = ag_s[ii];
        float tt[4]; bool ne[4];
#pragma unroll
        for (int k = 0; k < 4; k++) {
            int idx = nxt[k];
            if (isv0 && k == 0 && i >= 1) idx = 0;
            ne[k] = (idx == L_);
            tt[k] = ta[ne[k] ? (L_ - 1) : idx] - a;
        }
        *(float4*)&out_tte[(size_t)i * V_ + v0] = make_float4(tt[0], tt[1], tt[2], tt[3]);

        size_t mbase = (size_t)i * NBIN * V_ + v0;
#pragma unroll
        for (int n = 0; n < NBIN; n++) {
            float lo = 1.25f * n;
            float hi = 1.25f * (n + 1);
            float4 m;
            m.x = ((tt[0] >= lo && tt[0] < hi) || ne[0]) ? 1.0f : 0.0f;
            m.y = ((tt[1] >= lo && tt[1] < hi) || ne[1]) ? 1.0f : 0.0f;
            m.z = ((tt[2] >= lo && tt[2] < hi) || ne[2]) ? 1.0f : 0.0f;
            m.w = ((tt[3] >= lo && tt[3] < hi) || ne[3]) ? 1.0f : 0.0f;
            *(float4*)&out_mask[mbase + (size_t)n * V_] = m;
        }
    }
}

// ---------------------------------------------------------------------------
// Kernel 3: logits as a standard GEMM.
// m = row*8 + bin (A[m][h] = g_x[row*256 + h*8 + bin]), so C[m][v] IS the
// logits layout.  M=32768, N=1280, K=32.  128x128 tile, 256 threads,
// 8x8 micro-tile via diagonal-packed FFMA2.  Per k: 4 LDS.128 : 32 FFMA2.
// ---------------------------------------------------------------------------
__global__ __launch_bounds__(256) void k_gemm2(const float* __restrict__ W2,
                                               float* __restrict__ out) {
    __shared__ float As[32][132];   // [h][m_local]
    __shared__ float Bs[32][132];   // [h][v_local]
    int tid = threadIdx.x;
    int tx = tid & 15, ty = tid >> 4;
    int v0 = blockIdx.x * 128;      // 0..9
    int m0 = blockIdx.y * 128;      // 0..255

    // A tile: 16 g_x rows (= 128 m) x 256 floats, contiguous 16KB.
    // g_x[r][h*8+n] -> As[h][rl*8+n]
    const float4* xsrc = (const float4*)(g_x + (size_t)(m0 >> 3) * 256);
#pragma unroll
    for (int p = 0; p < 4; p++) {
        int idx = tid + p * 256;            // float4 index, 1024 total
        float4 v4 = xsrc[idx];
        int rl = idx >> 6;                  // 0..15
        int rem = idx & 63;                 // h*2 + n4
        int h = rem >> 1, n4 = (rem & 1) << 2;
        *(float4*)&As[h][rl * 8 + n4] = v4;
    }
    // B tile: W2[h][v0+vl], 32x128
#pragma unroll
    for (int p = 0; p < 4; p++) {
        int idx = tid + p * 256;            // float4 index over 32x32
        int h = idx >> 5, v4 = (idx & 31) << 2;
        *(float4*)&Bs[h][v4] = *(const float4*)&W2[(size_t)h * V_ + v0 + v4];
    }
    __syncthreads();

    u64 acc[4][8];
#pragma unroll
    for (int i = 0; i < 4; i++)
#pragma unroll
        for (int j = 0; j < 8; j++) acc[i][j] = 0;

#pragma unroll 8
    for (int k = 0; k < 32; k++) {
        F4U2 a0, a1, b0, b1;
        a0.f = *(const float4*)&As[k][ty * 8];
        a1.f = *(const float4*)&As[k][ty * 8 + 4];
        b0.f = *(const float4*)&Bs[k][tx * 8];
        b1.f = *(const float4*)&Bs[k][tx * 8 + 4];
        u64 ap[4] = {a0.u[0], a0.u[1], a1.u[0], a1.u[1]};
        u64 bp[8];
        bp[0] = b0.u[0];            bp[1] = pk(b0.f.y, b0.f.z);
        bp[2] = b0.u[1];            bp[3] = pk(b0.f.w, b0.f.x);
        bp[4] = b1.u[0];            bp[5] = pk(b1.f.y, b1.f.z);
        bp[6] = b1.u[1];            bp[7] = pk(b1.f.w, b1.f.x);
#pragma unroll
        for (int mp = 0; mp < 4; mp++)
#pragma unroll
            for (int j = 0; j < 8; j++)
                fma2(acc[mp][j], ap[mp], bp[j]);
    }

    // Decode diagonal pairs into c[8][8]
    float c[8][8];
#pragma unroll
    for (int mp = 0; mp < 4; mp++) {
        upk(acc[mp][0], c[2*mp][0], c[2*mp+1][1]);
        upk(acc[mp][1], c[2*mp][1], c[2*mp+1][2]);
        upk(acc[mp][2], c[2*mp][2], c[2*mp+1][3]);
        upk(acc[mp][3], c[2*mp][3], c[2*mp+1][0]);
        upk(acc[mp][4], c[2*mp][4], c[2*mp+1][5]);
        upk(acc[mp][5], c[2*mp][5], c[2*mp+1][6]);
        upk(acc[mp][6], c[2*mp][6], c[2*mp+1][7]);
        upk(acc[mp][7], c[2*mp][7], c[2*mp+1][4]);
    }

#pragma unroll
    for (int mr = 0; mr < 8; mr++) {
        size_t off = (size_t)(m0 + ty * 8 + mr) * V_ + v0 + tx * 8;
        *(float4*)&out[off]     = make_float4(c[mr][0], c[mr][1], c[mr][2], c[mr][3]);
        *(float4*)&out[off + 4] = make_float4(c[mr][4], c[mr][5], c[mr][6], c[mr][7]);
    }
}

// ---------------------------------------------------------------------------
static cudaStream_t g_s2;
static cudaEvent_t g_e1, g_e2;
static struct StreamInit {
    StreamInit() {
        cudaStreamCreateWithFlags(&g_s2, cudaStreamNonBlocking);
        cudaEventCreateWithFlags(&g_e1, cudaEventDisableTiming);
        cudaEventCreateWithFlags(&g_e2, cudaEventDisableTiming);
    }
} g_stream_init;

extern "C" void kernel_launch(void* const* d_in, const int* in_sizes, int n_in,
                              void* d_out, int out_size) {
    const float* h       = (const float*)d_in[0];  // (B,L,768)
    const float* age     = (const float*)d_in[1];  // (B,L)
    const float* tage    = (const float*)d_in[2];  // (B,L)
    const int*   targets = (const int*)d_in[4];    // (B,L) int32
    const float* W1      = (const float*)d_in[5];  // (768,256)
    const float* W2      = (const float*)d_in[6];  // (32,1280)
    float* out = (float*)d_out;

    // Fork: tte/mask path (store-BW bound) overlaps GEMM path (fma bound).
    cudaEventRecord(g_e1, 0);
    cudaStreamWaitEvent(g_s2, g_e1, 0);
    k_seed<<<dim3(5, B_), 256, 0, g_s2>>>(targets);
    k_tte_write<<<dim3(2, 32, B_), 160, 0, g_s2>>>(targets, age, tage, out);

    k_gemm1<<<dim3(4, 32), 256>>>(h, W1);
    k_gemm2<<<dim3(10, 256), 256>>>(W2, out);

    cudaEventRecord(g_e2, g_s2);
    cudaStreamWaitEvent(0, g_e2, 0);
}